// round 1
// baseline (speedup 1.0000x reference)
#include <cuda_runtime.h>
#include <math.h>

#define B_TOTAL 131072
#define Hh 128
#define Dd 256
#define Ee 128
#define G3H 384
#define MT 32
#define NTHR 256

// Transposed GRU weights (k-major [E][3H]) — device scratch, no allocation.
__device__ float g_wihT[Ee * G3H];
__device__ float g_whhT[Hh * G3H];

__global__ void transpose_gru_kernel(const float* __restrict__ wih,
                                     const float* __restrict__ whh) {
    int idx = blockIdx.x * blockDim.x + threadIdx.x;
    if (idx < Ee * G3H) {
        int e = idx / G3H, j = idx % G3H;
        g_wihT[idx] = wih[j * Ee + e];
        g_whhT[idx] = whh[j * Hh + e];
    }
}

// ---------------------------------------------------------------------------
// evolve: one RK4 (3/8 rule) step per row. 32 rows/CTA, 8 warps, 4 rows/warp.
// All smem tiles are warp-private in rows -> no in-loop __syncthreads.
// ---------------------------------------------------------------------------
#define EV_SMEM_FLOATS 50080
__global__ void __launch_bounds__(NTHR, 1) evolve_kernel(
    const float* __restrict__ hidden, const float* __restrict__ dts,
    const float* __restrict__ w1, const float* __restrict__ b1,
    const float* __restrict__ lnw, const float* __restrict__ lnb,
    const float* __restrict__ w2, const float* __restrict__ b2,
    float* __restrict__ evolved)
{
    extern __shared__ float sm[];
    float* w1_s  = sm;              // 32768 floats (128KB), resident all stages
    float* h_s   = sm + 32768;      // 32x128
    float* arg_s = sm + 36864;      // 32x128
    float* a_s   = sm + 40960;      // 32x256
    float* b1_s  = sm + 49152;      // 256
    float* lnw_s = sm + 49408;      // 256
    float* lnb_s = sm + 49664;      // 256
    float* b2_s  = sm + 49920;      // 128
    float* dt_s  = sm + 50048;      // 32

    const int tid  = threadIdx.x;
    const int lane = tid & 31;
    const int wrp  = tid >> 5;
    const int r0   = wrp * 4;                       // local row base (4 rows/warp)
    const size_t row0 = (size_t)blockIdx.x * MT;

    // ---- stage weights + tile ----
    {
        const float4* src = reinterpret_cast<const float4*>(w1);
        float4* dst = reinterpret_cast<float4*>(w1_s);
        #pragma unroll
        for (int t = 0; t < 32; ++t) dst[tid + t * NTHR] = src[tid + t * NTHR];
    }
    {
        const float4* src = reinterpret_cast<const float4*>(hidden + row0 * Hh);
        float4* dh = reinterpret_cast<float4*>(h_s);
        float4* da = reinterpret_cast<float4*>(arg_s);
        #pragma unroll
        for (int t = 0; t < 4; ++t) {
            float4 v = src[tid + t * NTHR];
            dh[tid + t * NTHR] = v;
            da[tid + t * NTHR] = v;
        }
    }
    if (tid < 256) { b1_s[tid] = b1[tid]; lnw_s[tid] = lnw[tid]; lnb_s[tid] = lnb[tid]; }
    if (tid < 128) b2_s[tid] = b2[tid];
    if (tid < 32)  dt_s[tid] = fmaxf(dts[row0 + tid], 0.0f);
    __syncthreads();

    float k1r[4][4], k2r[4][4], accr[4][4];

    #pragma unroll 1
    for (int s = 0; s < 4; ++s) {
        // ---- mm1: u[4 rows][8 cols] = arg @ w1 + b1 ----
        float u[4][8];
        #pragma unroll
        for (int i = 0; i < 4; ++i)
            #pragma unroll
            for (int j = 0; j < 8; ++j) u[i][j] = b1_s[lane * 8 + j];

        const float4* w1v = reinterpret_cast<const float4*>(w1_s);
        #pragma unroll 2
        for (int k = 0; k < Hh; k += 4) {
            float4 av[4];
            #pragma unroll
            for (int i = 0; i < 4; ++i)
                av[i] = *reinterpret_cast<const float4*>(arg_s + (r0 + i) * Hh + k);
            #pragma unroll
            for (int kk = 0; kk < 4; ++kk) {
                float4 w0 = w1v[(k + kk) * 64 + lane * 2];
                float4 w1q = w1v[(k + kk) * 64 + lane * 2 + 1];
                float wv[8] = {w0.x, w0.y, w0.z, w0.w, w1q.x, w1q.y, w1q.z, w1q.w};
                #pragma unroll
                for (int i = 0; i < 4; ++i) {
                    float a = (kk == 0) ? av[i].x : (kk == 1) ? av[i].y
                            : (kk == 2) ? av[i].z : av[i].w;
                    #pragma unroll
                    for (int j = 0; j < 8; ++j) u[i][j] = fmaf(a, wv[j], u[i][j]);
                }
            }
        }

        // ---- LayerNorm + exact GELU, a -> smem ----
        #pragma unroll
        for (int i = 0; i < 4; ++i) {
            float s1 = 0.f, s2 = 0.f;
            #pragma unroll
            for (int j = 0; j < 8; ++j) { s1 += u[i][j]; s2 += u[i][j] * u[i][j]; }
            #pragma unroll
            for (int off = 16; off >= 1; off >>= 1) {
                s1 += __shfl_xor_sync(0xffffffffu, s1, off);
                s2 += __shfl_xor_sync(0xffffffffu, s2, off);
            }
            float mu   = s1 * (1.0f / Dd);
            float var  = s2 * (1.0f / Dd) - mu * mu;
            float rstd = rsqrtf(var + 1e-5f);
            #pragma unroll
            for (int j = 0; j < 8; ++j) {
                int c = lane * 8 + j;
                float v = (u[i][j] - mu) * rstd * lnw_s[c] + lnb_s[c];
                a_s[(r0 + i) * Dd + c] = v * normcdff(v);   // exact gelu
            }
        }
        __syncwarp();   // a_s rows are warp-private; warp-level ordering suffices

        // ---- mm2: k[4 rows][4 cols] = a @ w2 + b2 (w2 streamed from L2) ----
        float kv[4][4];
        #pragma unroll
        for (int i = 0; i < 4; ++i)
            #pragma unroll
            for (int j = 0; j < 4; ++j) kv[i][j] = b2_s[lane * 4 + j];

        const float4* w2v = reinterpret_cast<const float4*>(w2);
        #pragma unroll 2
        for (int d = 0; d < Dd; d += 4) {
            float4 av[4];
            #pragma unroll
            for (int i = 0; i < 4; ++i)
                av[i] = *reinterpret_cast<const float4*>(a_s + (r0 + i) * Dd + d);
            #pragma unroll
            for (int dd = 0; dd < 4; ++dd) {
                float4 wq = __ldg(w2v + (d + dd) * 32 + lane);
                #pragma unroll
                for (int i = 0; i < 4; ++i) {
                    float a = (dd == 0) ? av[i].x : (dd == 1) ? av[i].y
                            : (dd == 2) ? av[i].z : av[i].w;
                    kv[i][0] = fmaf(a, wq.x, kv[i][0]);
                    kv[i][1] = fmaf(a, wq.y, kv[i][1]);
                    kv[i][2] = fmaf(a, wq.z, kv[i][2]);
                    kv[i][3] = fmaf(a, wq.w, kv[i][3]);
                }
            }
        }

        // ---- RK4 stage combine (warp-private rows; same thread owns same elems) ----
        if (s == 0) {
            #pragma unroll
            for (int i = 0; i < 4; ++i) {
                float dt = dt_s[r0 + i];
                #pragma unroll
                for (int j = 0; j < 4; ++j) {
                    int c = lane * 4 + j;
                    k1r[i][j] = kv[i][j];
                    accr[i][j] = kv[i][j];
                    arg_s[(r0 + i) * Hh + c] =
                        h_s[(r0 + i) * Hh + c] + dt * (kv[i][j] * (1.0f / 3.0f));
                }
            }
        } else if (s == 1) {
            #pragma unroll
            for (int i = 0; i < 4; ++i) {
                float dt = dt_s[r0 + i];
                #pragma unroll
                for (int j = 0; j < 4; ++j) {
                    int c = lane * 4 + j;
                    k2r[i][j] = kv[i][j];
                    accr[i][j] += 3.0f * kv[i][j];
                    arg_s[(r0 + i) * Hh + c] =
                        h_s[(r0 + i) * Hh + c] + dt * (kv[i][j] - k1r[i][j] * (1.0f / 3.0f));
                }
            }
        } else if (s == 2) {
            #pragma unroll
            for (int i = 0; i < 4; ++i) {
                float dt = dt_s[r0 + i];
                #pragma unroll
                for (int j = 0; j < 4; ++j) {
                    int c = lane * 4 + j;
                    accr[i][j] += 3.0f * kv[i][j];
                    arg_s[(r0 + i) * Hh + c] =
                        h_s[(r0 + i) * Hh + c] + dt * (k1r[i][j] - k2r[i][j] + kv[i][j]);
                }
            }
        } else {
            #pragma unroll
            for (int i = 0; i < 4; ++i) {
                float dt = dt_s[r0 + i];
                float4 o;
                float* op = reinterpret_cast<float*>(&o);
                #pragma unroll
                for (int j = 0; j < 4; ++j) {
                    int c = lane * 4 + j;
                    float hv = h_s[(r0 + i) * Hh + c];
                    float a = accr[i][j] + kv[i][j];
                    op[j] = (dt > 0.0f) ? (hv + dt * a * 0.125f) : hv;
                }
                *reinterpret_cast<float4*>(evolved + (row0 + r0 + i) * Hh + lane * 4) = o;
            }
        }
        __syncwarp();   // arg_s written before next stage's mm1 reads (same warp)
    }
}

// ---------------------------------------------------------------------------
// GRU update. Lane owns gate cols j = lane + 32m, m<12 -> r/z/n for the same
// hidden index live on the same lane (no cross-lane gate exchange).
// ---------------------------------------------------------------------------
#define GRU_SMEM_FLOATS 57344
__global__ void __launch_bounds__(NTHR, 1) gru_kernel(
    const float* __restrict__ evolved, const float* __restrict__ obs,
    const int* __restrict__ mask,
    const float* __restrict__ bih, const float* __restrict__ bhh,
    float* __restrict__ updated)
{
    extern __shared__ float sm[];
    float* w_s   = sm;              // 128x384 (192KB) — WihT then WhhT
    float* obs_s = sm + 49152;      // 32x128
    float* ev_s  = sm + 53248;      // 32x128

    const int tid  = threadIdx.x;
    const int lane = tid & 31;
    const int wrp  = tid >> 5;
    const int r0   = wrp * 4;
    const size_t row0 = (size_t)blockIdx.x * MT;

    {
        const float4* so = reinterpret_cast<const float4*>(obs + row0 * Ee);
        const float4* se = reinterpret_cast<const float4*>(evolved + row0 * Hh);
        float4* dobs = reinterpret_cast<float4*>(obs_s);
        float4* dev  = reinterpret_cast<float4*>(ev_s);
        #pragma unroll
        for (int t = 0; t < 4; ++t) {
            dobs[tid + t * NTHR] = so[tid + t * NTHR];
            dev[tid + t * NTHR]  = se[tid + t * NTHR];
        }
    }
    {
        const float4* src = reinterpret_cast<const float4*>(g_wihT);
        float4* dst = reinterpret_cast<float4*>(w_s);
        #pragma unroll
        for (int t = 0; t < 48; ++t) dst[tid + t * NTHR] = src[tid + t * NTHR];
    }
    __syncthreads();

    // gi = obs @ WihT + bih
    float gi[4][12];
    #pragma unroll
    for (int m = 0; m < 12; ++m) {
        float b = __ldg(bih + lane + 32 * m);
        #pragma unroll
        for (int i = 0; i < 4; ++i) gi[i][m] = b;
    }
    #pragma unroll 2
    for (int e = 0; e < Ee; e += 4) {
        float4 ov[4];
        #pragma unroll
        for (int i = 0; i < 4; ++i)
            ov[i] = *reinterpret_cast<const float4*>(obs_s + (r0 + i) * Ee + e);
        #pragma unroll
        for (int ee = 0; ee < 4; ++ee) {
            float wv[12];
            #pragma unroll
            for (int m = 0; m < 12; ++m) wv[m] = w_s[(e + ee) * G3H + lane + 32 * m];
            #pragma unroll
            for (int i = 0; i < 4; ++i) {
                float a = (ee == 0) ? ov[i].x : (ee == 1) ? ov[i].y
                        : (ee == 2) ? ov[i].z : ov[i].w;
                #pragma unroll
                for (int m = 0; m < 12; ++m) gi[i][m] = fmaf(a, wv[m], gi[i][m]);
            }
        }
    }
    __syncthreads();    // all warps done with WihT
    {
        const float4* src = reinterpret_cast<const float4*>(g_whhT);
        float4* dst = reinterpret_cast<float4*>(w_s);
        #pragma unroll
        for (int t = 0; t < 48; ++t) dst[tid + t * NTHR] = src[tid + t * NTHR];
    }
    __syncthreads();

    // gh = evolved @ WhhT + bhh
    float gh[4][12];
    #pragma unroll
    for (int m = 0; m < 12; ++m) {
        float b = __ldg(bhh + lane + 32 * m);
        #pragma unroll
        for (int i = 0; i < 4; ++i) gh[i][m] = b;
    }
    #pragma unroll 2
    for (int e = 0; e < Hh; e += 4) {
        float4 ov[4];
        #pragma unroll
        for (int i = 0; i < 4; ++i)
            ov[i] = *reinterpret_cast<const float4*>(ev_s + (r0 + i) * Hh + e);
        #pragma unroll
        for (int ee = 0; ee < 4; ++ee) {
            float wv[12];
            #pragma unroll
            for (int m = 0; m < 12; ++m) wv[m] = w_s[(e + ee) * G3H + lane + 32 * m];
            #pragma unroll
            for (int i = 0; i < 4; ++i) {
                float a = (ee == 0) ? ov[i].x : (ee == 1) ? ov[i].y
                        : (ee == 2) ? ov[i].z : ov[i].w;
                #pragma unroll
                for (int m = 0; m < 12; ++m) gh[i][m] = fmaf(a, wv[m], gh[i][m]);
            }
        }
    }

    // gates + select
    #pragma unroll
    for (int i = 0; i < 4; ++i) {
        size_t grow = row0 + r0 + i;
        int msk = __ldg(mask + grow);
        #pragma unroll
        for (int m = 0; m < 4; ++m) {
            int hidx = lane + 32 * m;
            float r = 1.0f / (1.0f + __expf(-(gi[i][m]     + gh[i][m])));
            float z = 1.0f / (1.0f + __expf(-(gi[i][m + 4] + gh[i][m + 4])));
            float n = tanhf(gi[i][m + 8] + r * gh[i][m + 8]);
            float ev = ev_s[(r0 + i) * Hh + hidx];
            float g  = (1.0f - z) * n + z * ev;
            updated[grow * Hh + hidx] = (msk > 0) ? g : ev;
        }
    }
}

// ---------------------------------------------------------------------------
extern "C" void kernel_launch(void* const* d_in, const int* in_sizes, int n_in,
                              void* d_out, int out_size)
{
    const float* hidden = (const float*)d_in[0];
    const float* dts    = (const float*)d_in[1];
    const float* obs    = (const float*)d_in[2];
    const int*   mask   = (const int*)d_in[3];
    const float* w1     = (const float*)d_in[4];
    const float* b1     = (const float*)d_in[5];
    const float* lnw    = (const float*)d_in[6];
    const float* lnb    = (const float*)d_in[7];
    const float* w2     = (const float*)d_in[8];
    const float* b2     = (const float*)d_in[9];
    const float* wih    = (const float*)d_in[10];
    const float* whh    = (const float*)d_in[11];
    const float* bih    = (const float*)d_in[12];
    const float* bhh    = (const float*)d_in[13];

    float* evolved = (float*)d_out;
    float* updated = evolved + (size_t)B_TOTAL * Hh;

    cudaFuncSetAttribute(evolve_kernel, cudaFuncAttributeMaxDynamicSharedMemorySize,
                         EV_SMEM_FLOATS * 4);
    cudaFuncSetAttribute(gru_kernel, cudaFuncAttributeMaxDynamicSharedMemorySize,
                         GRU_SMEM_FLOATS * 4);

    transpose_gru_kernel<<<(Ee * G3H + 255) / 256, 256>>>(wih, whh);
    evolve_kernel<<<B_TOTAL / MT, NTHR, EV_SMEM_FLOATS * 4>>>(
        hidden, dts, w1, b1, lnw, lnb, w2, b2, evolved);
    gru_kernel<<<B_TOTAL / MT, NTHR, GRU_SMEM_FLOATS * 4>>>(
        evolved, obs, mask, bih, bhh, updated);
}